// round 4
// baseline (speedup 1.0000x reference)
#include <cuda_runtime.h>
#include <cuda_fp16.h>
#include <cstdint>
#include <math.h>

#define C_CELLS 128
#define H_DIM   256
#define CE_DIM  64
#define MAXG    2048

// ---------------- device scratch (allocation-free rule) ----------------
__device__ float g_hidden[C_CELLS * H_DIM];
__device__ float g_Abuf[C_CELLS * H_DIM];            // ce @ W1[1:65]  [c][h]
__device__ float g_Bbuf[MAXG * H_DIM];               // gene-side layer1 bias [g][h]
__device__ __align__(16) __half g_w2t[H_DIM * H_DIM]; // fp16 W2a^T [n][k] plain

__device__ __forceinline__ float eluf(float x) {
    return x > 0.f ? x : (__expf(x) - 1.f);
}
__device__ __forceinline__ uint32_t smem_to_u32(const void* p) {
    uint32_t a;
    asm("{ .reg .u64 t; cvta.to.shared.u64 t, %1; cvt.u32.u64 %0, t; }" : "=r"(a) : "l"(p));
    return a;
}
__device__ __forceinline__ void ldsm4(uint32_t* r, uint32_t addr) {
    asm volatile("ldmatrix.sync.aligned.m8n8.x4.shared.b16 {%0,%1,%2,%3}, [%4];"
                 : "=r"(r[0]), "=r"(r[1]), "=r"(r[2]), "=r"(r[3]) : "r"(addr));
}
__device__ __forceinline__ void mma16816(float* c, const uint32_t* a, const uint32_t* b) {
    asm volatile("mma.sync.aligned.m16n8k16.row.col.f32.f16.f16.f32 "
                 "{%0,%1,%2,%3}, {%4,%5,%6,%7}, {%8,%9}, {%0,%1,%2,%3};"
                 : "+f"(c[0]), "+f"(c[1]), "+f"(c[2]), "+f"(c[3])
                 : "r"(a[0]), "r"(a[1]), "r"(a[2]), "r"(a[3]), "r"(b[0]), "r"(b[1]));
}
__device__ __forceinline__ void sts16(uint32_t addr, __half v) {
    unsigned short u = __half_as_ushort(v);
    asm volatile("st.shared.u16 [%0], %1;" :: "r"(addr), "h"(u) : "memory");
}
#define NBSYNC(id, n) asm volatile("bar.sync %0, %1;"   :: "r"(id), "r"(n) : "memory")
#define NBARR(id, n)  asm volatile("bar.arrive %0, %1;" :: "r"(id), "r"(n) : "memory")
#define MEMBAR_CTA()  asm volatile("membar.cta;" ::: "memory")

// swizzles (computed on tile-local byte offsets)
#define SWZ256(b) ((b) ^ (((b) >> 4) & 0x70))   // 256B rows: XOR bits[4:6] with row&7
#define SWZ512(b) ((b) ^ (((b) >> 5) & 0x70))   // 512B rows

// ---------------- SMEM layout (byte offsets in dynamic smem) ----------------
#define SM_W2T   0          // 256 x 512B swizzled fp16      (131072)
#define SM_BUF0  131072     // h1 chunk0: 128 x 256B swizzled (32768)
#define SM_BUF1  163840     // h1 chunk1                      (32768)
#define SM_CTRL  196608     // 128 f32
#define SM_P1    197120     // 256 f32
#define SM_R     198144     // 256 f32
#define SM_W3A   199168     // 256 f32
#define SM_LOGIT 200192     // 128 f32
#define SM_RED   200704     // 32 f32
#define SM_TOTAL 200832

// named barrier ids
#define B_EMPTY0 1
#define B_FULL0  2
#define B_EMPTY1 3
#define B_FULL1  4
#define B_PROD   5
#define B_RREADY 6
#define B_CONS   7

// ---------------------------------------------------------------------------
// K1: hidden[c,h] = elu(ctrl@ce_w1 + b1), tiled
// ---------------------------------------------------------------------------
__global__ void k_hidden(const float* __restrict__ ctrl, const float* __restrict__ w,
                         const float* __restrict__ b, int G) {
    extern __shared__ float s[];       // [8][G]
    const int t = threadIdx.x;
    const int hb = blockIdx.x, cb = blockIdx.y;
    for (int i = t; i < 8 * G; i += 256) {
        int cl = i / G, k = i - cl * G;
        s[cl * G + k] = ctrl[(cb * 8 + cl) * G + k];
    }
    __syncthreads();
    const int hl = t & 31, cl = t >> 5;
    const int h = hb * 32 + hl;
    const float* sc = s + cl * G;
    float a0 = 0.f, a1 = 0.f, a2 = 0.f, a3 = 0.f;
    int k = 0;
    for (; k + 3 < G; k += 4) {
        a0 = fmaf(sc[k+0], w[(k+0) * H_DIM + h], a0);
        a1 = fmaf(sc[k+1], w[(k+1) * H_DIM + h], a1);
        a2 = fmaf(sc[k+2], w[(k+2) * H_DIM + h], a2);
        a3 = fmaf(sc[k+3], w[(k+3) * H_DIM + h], a3);
    }
    for (; k < G; k++) a0 = fmaf(sc[k], w[k * H_DIM + h], a0);
    g_hidden[(cb * 8 + cl) * H_DIM + h] = eluf((a0 + a1) + (a2 + a3) + b[h]);
}

// ---------------------------------------------------------------------------
// K2: ce = hidden @ ce_w2 + ce_b2 ; A = ce @ W1[1:65]
// ---------------------------------------------------------------------------
__global__ void k_ceA(const float* __restrict__ ce_w2, const float* __restrict__ ce_b2,
                      const float* __restrict__ gw1) {
    __shared__ float s_hid[H_DIM];
    __shared__ float s_ce[CE_DIM];
    int c = blockIdx.x, t = threadIdx.x;
    s_hid[t] = g_hidden[c * H_DIM + t];
    __syncthreads();
    if (t < CE_DIM) {
        float a = ce_b2[t];
        #pragma unroll 4
        for (int k = 0; k < H_DIM; k++) a = fmaf(s_hid[k], ce_w2[k * CE_DIM + t], a);
        s_ce[t] = a;
    }
    __syncthreads();
    float a = 0.f;
    #pragma unroll
    for (int j = 0; j < CE_DIM; j++) a = fmaf(s_ce[j], gw1[(1 + j) * H_DIM + t], a);
    g_Abuf[c * H_DIM + t] = a;
}

// ---------------------------------------------------------------------------
// K3: B[g,:] = ge@W1[65:129] + shift*W1[129] + C*W1[130] + b1
// ---------------------------------------------------------------------------
__global__ void k_B(const float* __restrict__ gene_table, const float* __restrict__ shift_vec,
                    const int* __restrict__ gidx, const float* __restrict__ gw1,
                    const float* __restrict__ gb1) {
    __shared__ float s_ge[CE_DIM];
    __shared__ float s_shift;
    int g = blockIdx.x, t = threadIdx.x;
    int gi = gidx[g];
    if (t < CE_DIM) s_ge[t] = gene_table[gi * CE_DIM + t];
    if (t == 0) s_shift = shift_vec[gi];
    __syncthreads();
    float a = gb1[t] + s_shift * gw1[129 * H_DIM + t] + (float)C_CELLS * gw1[130 * H_DIM + t];
    #pragma unroll
    for (int j = 0; j < CE_DIM; j++) a = fmaf(s_ge[j], gw1[(65 + j) * H_DIM + t], a);
    g_Bbuf[g * H_DIM + t] = a;
}

// ---------------------------------------------------------------------------
// K_prep: fp16 image of W2a^T: g_w2t[n][k] = g_w2[k][n]  (plain layout)
// ---------------------------------------------------------------------------
__global__ void k_prep(const float* __restrict__ gw2) {
    int n = blockIdx.x, h = threadIdx.x;
    g_w2t[n * H_DIM + h] = __float2half(gw2[h * H_DIM + n]);
}

// ---------------------------------------------------------------------------
// consumer GEMM over one K-chunk (128 k) into acc[2][16][4]
// ---------------------------------------------------------------------------
__device__ __forceinline__ void gemm_chunk(float acc[2][16][4], uint32_t smem_u,
                                           uint32_t buf_off, int ck,
                                           uint32_t a_rb, uint32_t b_rb) {
    #pragma unroll
    for (int ksl = 0; ksl < 8; ksl++) {
        uint32_t a0o = a_rb + (uint32_t)ksl * 32;
        uint32_t a1o = a0o + 16u * 256u;
        uint32_t a[2][4];
        ldsm4(a[0], smem_u + buf_off + SWZ256(a0o));
        ldsm4(a[1], smem_u + buf_off + SWZ256(a1o));
        uint32_t bk = b_rb + (uint32_t)(ck * 8 + ksl) * 32;
        #pragma unroll
        for (int j2 = 0; j2 < 8; j2++) {
            uint32_t bo = bk + (uint32_t)j2 * (16u * 512u);
            uint32_t b[4];
            ldsm4(b, smem_u + SM_W2T + SWZ512(bo));
            mma16816(acc[0][j2 * 2],     a[0], b);
            mma16816(acc[0][j2 * 2 + 1], a[0], b + 2);
            mma16816(acc[1][j2 * 2],     a[1], b);
            mma16816(acc[1][j2 * 2 + 1], a[1], b + 2);
        }
    }
}

// ---------------------------------------------------------------------------
// K_main: persistent warp-specialized pipeline.
// warps 0-7 (t<256): consumers (HMMA, epilogue, softmax, output)
// warps 8-11 (t>=256): producers (h1 fill, p1, r)
// ---------------------------------------------------------------------------
__global__ void __launch_bounds__(384, 1)
k_main(const float* __restrict__ ctrl, const int* __restrict__ gidx,
       const float* __restrict__ gw1, const float* __restrict__ gw2,
       const float* __restrict__ gb2, const float* __restrict__ gw3,
       float* __restrict__ out, int G, int Gc) {
    extern __shared__ char smem[];
    const uint32_t smem_u = smem_to_u32(smem);
    const int t = threadIdx.x;

    // ---- one-time init: swizzled W2T copy, constants, logit zero ----
    {
        const uint4* src = (const uint4*)g_w2t;
        for (int idx = t; idx < 8192; idx += 384) {
            int n = idx >> 5, kq = idx & 31;
            uint32_t local = (uint32_t)n * 512u + (uint32_t)kq * 16u;
            *(uint4*)(smem + SM_W2T + SWZ512(local)) = src[idx];
        }
        float* s_w3a = (float*)(smem + SM_W3A);
        if (t < 256) s_w3a[t] = gw3[t];
        float* s_logit = (float*)(smem + SM_LOGIT);
        if (t < 128) s_logit[t] = 0.f;
    }
    __syncthreads();

    if (t < 256) {
        // ================= CONSUMERS =================
        const int lane = t & 31, w = t >> 5;
        const int mrow = (w & 3) * 32, nb = (w >> 2) * 128;
        const uint32_t a_rb = (uint32_t)(mrow + (lane & 15)) * 256u + (uint32_t)((lane >> 4) * 16);
        const uint32_t b_rb = (uint32_t)(nb + ((lane >> 4) << 3) + (lane & 7)) * 512u
                            + (uint32_t)(((lane >> 3) & 1) * 16);
        float* s_r     = (float*)(smem + SM_R);
        float* s_w3a   = (float*)(smem + SM_W3A);
        float* s_logit = (float*)(smem + SM_LOGIT);
        float* s_red   = (float*)(smem + SM_RED);

        for (int g = blockIdx.x; g < G; g += gridDim.x) {
            float acc[2][16][4];
            #pragma unroll
            for (int mh = 0; mh < 2; mh++)
                #pragma unroll
                for (int j = 0; j < 16; j++)
                    #pragma unroll
                    for (int q = 0; q < 4; q++) acc[mh][j][q] = 0.f;

            NBSYNC(B_FULL0, 384);
            gemm_chunk(acc, smem_u, SM_BUF0, 0, a_rb, b_rb);
            NBARR(B_EMPTY0, 384);
            NBSYNC(B_FULL1, 384);
            gemm_chunk(acc, smem_u, SM_BUF1, 1, a_rb, b_rb);
            NBSYNC(B_RREADY, 384);

            // epilogue: fold elu(x2 + r[n]) * w3a[n] -> per-cell partials
            float p[4] = {0.f, 0.f, 0.f, 0.f};
            const int nc = nb + ((lane & 3) << 1);
            #pragma unroll
            for (int mh = 0; mh < 2; mh++)
                #pragma unroll
                for (int j = 0; j < 16; j++) {
                    const int n0 = nc + j * 8;
                    const float w30 = s_w3a[n0], w31 = s_w3a[n0 + 1];
                    const float rr0 = s_r[n0],  rr1 = s_r[n0 + 1];
                    p[mh*2+0] = fmaf(eluf(acc[mh][j][0] + rr0), w30, p[mh*2+0]);
                    p[mh*2+0] = fmaf(eluf(acc[mh][j][1] + rr1), w31, p[mh*2+0]);
                    p[mh*2+1] = fmaf(eluf(acc[mh][j][2] + rr0), w30, p[mh*2+1]);
                    p[mh*2+1] = fmaf(eluf(acc[mh][j][3] + rr1), w31, p[mh*2+1]);
                }
            NBARR(B_EMPTY1, 384);   // buf1 + s_r reads complete

            #pragma unroll
            for (int i = 0; i < 4; i++) {
                p[i] += __shfl_xor_sync(0xffffffffu, p[i], 1);
                p[i] += __shfl_xor_sync(0xffffffffu, p[i], 2);
            }
            if ((lane & 3) == 0) {
                #pragma unroll
                for (int i = 0; i < 4; i++)
                    atomicAdd(&s_logit[mrow + (i >> 1) * 16 + (i & 1) * 8 + (lane >> 2)], p[i]);
            }
            NBSYNC(B_CONS, 256);

            // softmax over 128 cells (per-gene additive constants cancel)
            float l = (t < 128) ? s_logit[t] : -1e30f;
            float m = l;
            #pragma unroll
            for (int off = 16; off; off >>= 1) m = fmaxf(m, __shfl_xor_sync(0xffffffffu, m, off));
            if (lane == 0) s_red[w] = m;
            NBSYNC(B_CONS, 256);
            if (t < 32) {
                float mm = (t < 8) ? s_red[t] : -1e30f;
                #pragma unroll
                for (int off = 4; off; off >>= 1) mm = fmaxf(mm, __shfl_xor_sync(0xffffffffu, mm, off));
                if (t == 0) s_red[16] = mm;
            }
            NBSYNC(B_CONS, 256);
            const float M = s_red[16];
            float e = (t < 128) ? __expf(l - M) : 0.f;
            float s = e;
            #pragma unroll
            for (int off = 16; off; off >>= 1) s += __shfl_xor_sync(0xffffffffu, s, off);
            if (lane == 0) s_red[w] = s;
            NBSYNC(B_CONS, 256);
            if (t < 32) {
                float ss = (t < 8) ? s_red[t] : 0.f;
                #pragma unroll
                for (int off = 4; off; off >>= 1) ss += __shfl_xor_sync(0xffffffffu, ss, off);
                if (t == 0) s_red[17] = ss;
            }
            NBSYNC(B_CONS, 256);
            if (t < 128) {
                out[t * G + g] = e / s_red[17];
                s_logit[t] = 0.f;   // reset for next gene (fenced by next B_FULL0 sync)
            }
        }
    } else {
        // ================= PRODUCERS =================
        const int t2 = t - 256;                       // 0..127
        float* s_ctrl = (float*)(smem + SM_CTRL);
        float* s_p1   = (float*)(smem + SM_P1);
        float* s_r    = (float*)(smem + SM_R);
        const float w10a = gw1[t2];
        const float w10b = gw1[128 + t2];
        const float* w2b = gw2 + 256 * H_DIM;
        const uint32_t kb2 = (uint32_t)t2 * 2u;
        bool first = true;

        for (int g = blockIdx.x; g < G; g += gridDim.x) {
            const int gi = gidx[g];
            s_ctrl[t2] = ctrl[t2 * Gc + gi];
            NBSYNC(B_PROD, 128);

            // ---- chunk 0: h = t2 ----
            if (!first) NBSYNC(B_EMPTY0, 384);
            float sum0 = 0.f;
            {
                const float Brow = g_Bbuf[g * H_DIM + t2];
                const float* Ar = g_Abuf + t2;
                #pragma unroll 4
                for (int c = 0; c < 128; c++) {
                    float v = fmaf(s_ctrl[c], w10a, Ar[c * H_DIM] + Brow);
                    v = eluf(v);
                    sum0 += v;
                    uint32_t off = (uint32_t)c * 256u + (kb2 ^ ((uint32_t)(c & 7) << 4));
                    sts16(smem_u + SM_BUF0 + off, __float2half(v));
                }
            }
            MEMBAR_CTA();
            NBARR(B_FULL0, 384);

            // ---- chunk 1: h = 128 + t2 ----
            if (!first) NBSYNC(B_EMPTY1, 384);
            float sum1 = 0.f;
            {
                const float Brow = g_Bbuf[g * H_DIM + 128 + t2];
                const float* Ar = g_Abuf + 128 + t2;
                #pragma unroll 4
                for (int c = 0; c < 128; c++) {
                    float v = fmaf(s_ctrl[c], w10b, Ar[c * H_DIM] + Brow);
                    v = eluf(v);
                    sum1 += v;
                    uint32_t off = (uint32_t)c * 256u + (kb2 ^ ((uint32_t)(c & 7) << 4));
                    sts16(smem_u + SM_BUF1 + off, __float2half(v));
                }
            }
            MEMBAR_CTA();
            NBARR(B_FULL1, 384);
            first = false;

            // ---- p1, then r = p1 @ W2b + b2 ----
            s_p1[t2]       = sum0 * (1.f / (float)C_CELLS);
            s_p1[128 + t2] = sum1 * (1.f / (float)C_CELLS);
            NBSYNC(B_PROD, 128);
            float r0 = gb2[t2], r1 = gb2[128 + t2];
            #pragma unroll 4
            for (int h = 0; h < H_DIM; h++) {
                const float ph = s_p1[h];
                r0 = fmaf(ph, w2b[h * H_DIM + t2], r0);
                r1 = fmaf(ph, w2b[h * H_DIM + 128 + t2], r1);
            }
            s_r[t2] = r0;
            s_r[128 + t2] = r1;
            MEMBAR_CTA();
            NBARR(B_RREADY, 384);
        }
    }
}

// ---------------------------------------------------------------------------
extern "C" void kernel_launch(void* const* d_in, const int* in_sizes, int n_in,
                              void* d_out, int out_size) {
    const float* ctrl       = (const float*)d_in[0];
    const float* shift_vec  = (const float*)d_in[1];
    const int*   gidx       = (const int*)  d_in[2];
    const float* ce_w1      = (const float*)d_in[3];
    const float* ce_b1      = (const float*)d_in[4];
    const float* ce_w2      = (const float*)d_in[5];
    const float* ce_b2      = (const float*)d_in[6];
    const float* gene_table = (const float*)d_in[7];
    const float* g_w1       = (const float*)d_in[8];
    const float* g_b1       = (const float*)d_in[9];
    const float* g_w2       = (const float*)d_in[10];
    const float* g_b2       = (const float*)d_in[11];
    const float* g_w3       = (const float*)d_in[12];
    float* out = (float*)d_out;

    const int G  = in_sizes[2];
    const int Gc = in_sizes[0] / C_CELLS;

    int nsm = 148;
    cudaDeviceGetAttribute(&nsm, cudaDevAttrMultiProcessorCount, 0);
    if (nsm <= 0) nsm = 148;
    int grid = nsm < G ? nsm : G;

    cudaFuncSetAttribute(k_main, cudaFuncAttributeMaxDynamicSharedMemorySize, SM_TOTAL);
    cudaFuncSetAttribute(k_hidden, cudaFuncAttributeMaxDynamicSharedMemorySize, 8 * Gc * (int)sizeof(float));

    k_hidden<<<dim3(8, 16), 256, 8 * Gc * sizeof(float)>>>(ctrl, ce_w1, ce_b1, Gc);
    k_ceA<<<C_CELLS, H_DIM>>>(ce_w2, ce_b2, g_w1);
    k_B<<<G, H_DIM>>>(gene_table, shift_vec, gidx, g_w1, g_b1);
    k_prep<<<H_DIM, H_DIM>>>(g_w2);
    k_main<<<grid, 384, SM_TOTAL>>>(ctrl, gidx, g_w1, g_w2, g_b2, g_w3, out, G, Gc);
}

// round 5
// speedup vs baseline: 1.9872x; 1.9872x over previous
#include <cuda_runtime.h>
#include <cuda_fp16.h>
#include <cstdint>
#include <math.h>

#define C_CELLS 128
#define H_DIM   256
#define CE_DIM  64
#define MAXG    2048

// ---------------- device scratch (allocation-free rule) ----------------
__device__ float g_Abuf[C_CELLS * H_DIM];              // ce @ W1[1:65]  [c][h]
__device__ float g_Bbuf[MAXG * H_DIM];                 // gene-side layer1 bias [g][h]
__device__ __align__(16) __half g_w2t[H_DIM * H_DIM];  // fp16 W2a^T [n][k] plain

__device__ __forceinline__ float eluf(float x) {
    return x > 0.f ? x : (__expf(x) - 1.f);
}
__device__ __forceinline__ uint32_t smem_to_u32(const void* p) {
    uint32_t a;
    asm("{ .reg .u64 t; cvta.to.shared.u64 t, %1; cvt.u32.u64 %0, t; }" : "=r"(a) : "l"(p));
    return a;
}
__device__ __forceinline__ void ldsm4(uint32_t* r, uint32_t addr) {
    asm volatile("ldmatrix.sync.aligned.m8n8.x4.shared.b16 {%0,%1,%2,%3}, [%4];"
                 : "=r"(r[0]), "=r"(r[1]), "=r"(r[2]), "=r"(r[3]) : "r"(addr));
}
__device__ __forceinline__ void mma16816(float* c, const uint32_t* a, const uint32_t* b) {
    asm volatile("mma.sync.aligned.m16n8k16.row.col.f32.f16.f16.f32 "
                 "{%0,%1,%2,%3}, {%4,%5,%6,%7}, {%8,%9}, {%0,%1,%2,%3};"
                 : "+f"(c[0]), "+f"(c[1]), "+f"(c[2]), "+f"(c[3])
                 : "r"(a[0]), "r"(a[1]), "r"(a[2]), "r"(a[3]), "r"(b[0]), "r"(b[1]));
}
__device__ __forceinline__ void sts16(uint32_t addr, __half v) {
    unsigned short u = __half_as_ushort(v);
    asm volatile("st.shared.u16 [%0], %1;" :: "r"(addr), "h"(u) : "memory");
}

// swizzles on tile-local byte offsets (validated in R4)
#define SWZ256(b) ((b) ^ (((b) >> 4) & 0x70))   // 256B rows
#define SWZ512(b) ((b) ^ (((b) >> 5) & 0x70))   // 512B rows

// ---------------- SMEM layout (byte offsets) ----------------
#define SM_W2T   0          // 256 x 512B swizzled fp16      (131072)
#define SM_BUF0  131072     // h1 k-chunk0: 128 x 256B swz   (32768)
#define SM_BUF1  163840     // h1 k-chunk1                   (32768)
#define SM_CTRL  196608     // 128 f32
#define SM_PART  197120     // 512 f32
#define SM_P1    199168     // 256 f32
#define SM_R     200192     // 256 f32
#define SM_W3A   201216     // 256 f32
#define SM_LOGIT 202240     // 128 f32
#define SM_RED   202752     // 32 f32
#define SM_TOTAL 202880

// ---------------------------------------------------------------------------
// prep1: per-cell block: hidden[c,:]=elu(ctrl@ce_w1+b1); ce=hidden@ce_w2+b2;
//        A[c,:]=ce@W1[1:65]. grid 128 x 256 threads, smem = Gc floats.
// ---------------------------------------------------------------------------
__global__ void k_prep1(const float* __restrict__ ctrl, const float* __restrict__ w,
                        const float* __restrict__ b1,
                        const float* __restrict__ ce_w2, const float* __restrict__ ce_b2,
                        const float* __restrict__ gw1, int G) {
    extern __shared__ float s[];                 // [Gc] ctrl row, then reuse
    __shared__ float s_hid[H_DIM];
    __shared__ float s_ce[CE_DIM];
    const int c = blockIdx.x, t = threadIdx.x;
    for (int k = t; k < G; k += 256) s[k] = ctrl[c * G + k];
    __syncthreads();
    float a0 = 0.f, a1 = 0.f, a2 = 0.f, a3 = 0.f;
    int k = 0;
    for (; k + 3 < G; k += 4) {
        a0 = fmaf(s[k+0], w[(k+0) * H_DIM + t], a0);
        a1 = fmaf(s[k+1], w[(k+1) * H_DIM + t], a1);
        a2 = fmaf(s[k+2], w[(k+2) * H_DIM + t], a2);
        a3 = fmaf(s[k+3], w[(k+3) * H_DIM + t], a3);
    }
    for (; k < G; k++) a0 = fmaf(s[k], w[k * H_DIM + t], a0);
    s_hid[t] = eluf((a0 + a1) + (a2 + a3) + b1[t]);
    __syncthreads();
    if (t < CE_DIM) {
        float a = ce_b2[t];
        #pragma unroll 4
        for (int kk = 0; kk < H_DIM; kk++) a = fmaf(s_hid[kk], ce_w2[kk * CE_DIM + t], a);
        s_ce[t] = a;
    }
    __syncthreads();
    float a = 0.f;
    #pragma unroll
    for (int j = 0; j < CE_DIM; j++) a = fmaf(s_ce[j], gw1[(1 + j) * H_DIM + t], a);
    g_Abuf[c * H_DIM + t] = a;
}

// ---------------------------------------------------------------------------
// prep2: blocks [0,G): B rows; blocks [G, G+256): w2t rows.
// ---------------------------------------------------------------------------
__global__ void k_prep2(const float* __restrict__ gene_table, const float* __restrict__ shift_vec,
                        const int* __restrict__ gidx, const float* __restrict__ gw1,
                        const float* __restrict__ gb1, const float* __restrict__ gw2, int G) {
    const int t = threadIdx.x;
    if ((int)blockIdx.x < G) {
        __shared__ float s_ge[CE_DIM];
        __shared__ float s_shift;
        const int g = blockIdx.x;
        const int gi = gidx[g];
        if (t < CE_DIM) s_ge[t] = gene_table[gi * CE_DIM + t];
        if (t == 0) s_shift = shift_vec[gi];
        __syncthreads();
        float a = gb1[t] + s_shift * gw1[129 * H_DIM + t] + (float)C_CELLS * gw1[130 * H_DIM + t];
        #pragma unroll
        for (int j = 0; j < CE_DIM; j++) a = fmaf(s_ge[j], gw1[(65 + j) * H_DIM + t], a);
        g_Bbuf[g * H_DIM + t] = a;
    } else {
        const int n = blockIdx.x - G;
        g_w2t[n * H_DIM + t] = __float2half(gw2[t * H_DIM + n]);
    }
}

// ---------------------------------------------------------------------------
// k_main: persistent, all-warp phases, r overlapped with GEMM chunk0.
// 512 threads = 16 warps (4 m-groups x 4 n-groups, m32n64 per warp).
// ---------------------------------------------------------------------------
__global__ void __launch_bounds__(512, 1)
k_main(const float* __restrict__ ctrl, const int* __restrict__ gidx,
       const float* __restrict__ gw1, const float* __restrict__ gw2,
       const float* __restrict__ gb2, const float* __restrict__ gw3,
       float* __restrict__ out, int G, int Gc) {
    extern __shared__ char smem[];
    const uint32_t smem_u = smem_to_u32(smem);
    const int t = threadIdx.x;
    const int lane = t & 31, w = t >> 5;

    float* s_ctrl  = (float*)(smem + SM_CTRL);
    float* s_part  = (float*)(smem + SM_PART);
    float* s_p1    = (float*)(smem + SM_P1);
    float* s_r     = (float*)(smem + SM_R);
    float* s_w3a   = (float*)(smem + SM_W3A);
    float* s_logit = (float*)(smem + SM_LOGIT);
    float* s_red   = (float*)(smem + SM_RED);

    // ---- one-time init: swizzled W2T (512B rows), constants ----
    {
        const uint4* src = (const uint4*)g_w2t;
        for (int idx = t; idx < 8192; idx += 512) {
            int n = idx >> 5, kq = idx & 31;
            uint32_t local = (uint32_t)n * 512u + (uint32_t)kq * 16u;
            *(uint4*)(smem + SM_W2T + SWZ512(local)) = src[idx];
        }
        if (t < 256) s_w3a[t] = gw3[t];
        if (t < 128) s_logit[t] = 0.f;
    }
    __syncthreads();

    // ---- hoisted per-thread constants ----
    const int h   = t & 255, sub = t >> 8;           // pass1 assignment
    const float w10 = gw1[h];                        // W1 row 0 (static)
    const float* Ar = g_Abuf + h;
    const uint32_t stsbase = smem_u + (h < 128 ? SM_BUF0 : SM_BUF1);
    const uint32_t kb2 = (uint32_t)(h & 127) * 2u;

    const int mrow = (w & 3) * 32, nb = (w >> 2) * 64;
    const uint32_t a_rb = (uint32_t)(mrow + (lane & 15)) * 256u + (uint32_t)((lane >> 4) * 16);
    const uint32_t b_rb = (uint32_t)(nb + ((lane >> 4) << 3) + (lane & 7)) * 512u
                        + (uint32_t)(((lane >> 3) & 1) * 16);

    // r assignment: warp w computes cols [w*16, w*16+16), 2 lanes per col
    const int  rcol  = w * 16 + (lane >> 1);
    const int  rkh   = lane & 1;                     // k-half
    const float rbias = (rkh == 0) ? gb2[rcol] : 0.f;
    const float* w2bp = gw2 + 256 * H_DIM + rkh * 128 * H_DIM + rcol;

    for (int g = blockIdx.x; g < G; g += gridDim.x) {
        const int gi = gidx[g];
        if (t < 128) s_ctrl[t] = ctrl[t * Gc + gi];
        __syncthreads();

        // ---- pass1: h1 fp16 into BUF0/BUF1 + partial column sums ----
        {
            const float Brow = g_Bbuf[g * H_DIM + h];
            float sum = 0.f;
            #pragma unroll 4
            for (int cc = 0; cc < 64; cc++) {
                const int c = sub * 64 + cc;
                float v = fmaf(s_ctrl[c], w10, Ar[c * H_DIM] + Brow);
                v = eluf(v);
                sum += v;
                sts16(stsbase + (uint32_t)c * 256u + (kb2 ^ ((uint32_t)(c & 7) << 4)),
                      __float2half(v));
            }
            s_part[sub * 256 + h] = sum;
        }
        __syncthreads();
        if (t < 256) s_p1[t] = (s_part[t] + s_part[256 + t]) * (1.f / (float)C_CELLS);
        __syncthreads();

        // ---- GEMM (16 k-steps) with r interleaved into chunk0 ----
        float acc[2][8][4];
        #pragma unroll
        for (int mh = 0; mh < 2; mh++)
            #pragma unroll
            for (int j = 0; j < 8; j++)
                #pragma unroll
                for (int q = 0; q < 4; q++) acc[mh][j][q] = 0.f;

        float racc = rbias;
        #pragma unroll
        for (int ksl = 0; ksl < 8; ksl++) {        // chunk0: k 0..127 from BUF0
            uint32_t a0o = a_rb + (uint32_t)ksl * 32;
            uint32_t a[2][4];
            ldsm4(a[0], smem_u + SM_BUF0 + SWZ256(a0o));
            ldsm4(a[1], smem_u + SM_BUF0 + SWZ256(a0o + 16u * 256u));
            uint32_t bk = b_rb + (uint32_t)ksl * 32;
            #pragma unroll
            for (int j2 = 0; j2 < 4; j2++) {
                uint32_t b[4];
                ldsm4(b, smem_u + SM_W2T + SWZ512(bk + (uint32_t)j2 * (16u * 512u)));
                mma16816(acc[0][j2 * 2],     a[0], b);
                mma16816(acc[0][j2 * 2 + 1], a[0], b + 2);
                mma16816(acc[1][j2 * 2],     a[1], b);
                mma16816(acc[1][j2 * 2 + 1], a[1], b + 2);
            }
            // r: 16 MACs on the idle FMA pipe
            #pragma unroll
            for (int ii = 0; ii < 16; ii++) {
                const int i = ksl * 16 + ii;
                racc = fmaf(s_p1[rkh * 128 + i], w2bp[i * H_DIM], racc);
            }
        }
        #pragma unroll
        for (int ksl = 0; ksl < 8; ksl++) {        // chunk1: k 128..255 from BUF1
            uint32_t a0o = a_rb + (uint32_t)ksl * 32;
            uint32_t a[2][4];
            ldsm4(a[0], smem_u + SM_BUF1 + SWZ256(a0o));
            ldsm4(a[1], smem_u + SM_BUF1 + SWZ256(a0o + 16u * 256u));
            uint32_t bk = b_rb + (uint32_t)(8 + ksl) * 32;
            #pragma unroll
            for (int j2 = 0; j2 < 4; j2++) {
                uint32_t b[4];
                ldsm4(b, smem_u + SM_W2T + SWZ512(bk + (uint32_t)j2 * (16u * 512u)));
                mma16816(acc[0][j2 * 2],     a[0], b);
                mma16816(acc[0][j2 * 2 + 1], a[0], b + 2);
                mma16816(acc[1][j2 * 2],     a[1], b);
                mma16816(acc[1][j2 * 2 + 1], a[1], b + 2);
            }
        }
        racc += __shfl_xor_sync(0xffffffffu, racc, 1);
        if (rkh == 0) s_r[rcol] = racc;
        __syncthreads();                            // r visible; h1 bufs free

        // ---- epilogue: fold elu(x2 + r[n]) * w3a[n] -> per-cell logits ----
        {
            float p[4] = {0.f, 0.f, 0.f, 0.f};
            const int nc = nb + ((lane & 3) << 1);
            #pragma unroll
            for (int mh = 0; mh < 2; mh++)
                #pragma unroll
                for (int j = 0; j < 8; j++) {
                    const int n0 = nc + j * 8;
                    const float w30 = s_w3a[n0], w31 = s_w3a[n0 + 1];
                    const float rr0 = s_r[n0],  rr1 = s_r[n0 + 1];
                    p[mh*2+0] = fmaf(eluf(acc[mh][j][0] + rr0), w30, p[mh*2+0]);
                    p[mh*2+0] = fmaf(eluf(acc[mh][j][1] + rr1), w31, p[mh*2+0]);
                    p[mh*2+1] = fmaf(eluf(acc[mh][j][2] + rr0), w30, p[mh*2+1]);
                    p[mh*2+1] = fmaf(eluf(acc[mh][j][3] + rr1), w31, p[mh*2+1]);
                }
            #pragma unroll
            for (int i = 0; i < 4; i++) {
                p[i] += __shfl_xor_sync(0xffffffffu, p[i], 1);
                p[i] += __shfl_xor_sync(0xffffffffu, p[i], 2);
            }
            if ((lane & 3) == 0) {
                #pragma unroll
                for (int i = 0; i < 4; i++)
                    atomicAdd(&s_logit[mrow + (i >> 1) * 16 + (i & 1) * 8 + (lane >> 2)], p[i]);
            }
        }
        __syncthreads();

        // ---- softmax over 128 cells (per-gene additive constants cancel) ----
        {
            float l = (t < 128) ? s_logit[t] : -1e30f;
            float m = l;
            #pragma unroll
            for (int off = 16; off; off >>= 1) m = fmaxf(m, __shfl_xor_sync(0xffffffffu, m, off));
            if (lane == 0) s_red[w] = m;
            __syncthreads();
            if (t < 32) {
                float mm = (t < 16) ? s_red[t] : -1e30f;
                #pragma unroll
                for (int off = 8; off; off >>= 1) mm = fmaxf(mm, __shfl_xor_sync(0xffffffffu, mm, off));
                if (t == 0) s_red[16] = mm;
            }
            __syncthreads();
            const float M = s_red[16];
            float e = (t < 128) ? __expf(l - M) : 0.f;
            float s = e;
            #pragma unroll
            for (int off = 16; off; off >>= 1) s += __shfl_xor_sync(0xffffffffu, s, off);
            if (lane == 0) s_red[w] = s;
            __syncthreads();
            if (t < 32) {
                float ss = (t < 16) ? s_red[t] : 0.f;
                #pragma unroll
                for (int off = 8; off; off >>= 1) ss += __shfl_xor_sync(0xffffffffu, ss, off);
                if (t == 0) s_red[17] = ss;
            }
            __syncthreads();
            if (t < 128) {
                out[t * G + g] = e / s_red[17];
                s_logit[t] = 0.f;          // next-gene reset; guarded by next syncs
            }
        }
    }
}

// ---------------------------------------------------------------------------
extern "C" void kernel_launch(void* const* d_in, const int* in_sizes, int n_in,
                              void* d_out, int out_size) {
    const float* ctrl       = (const float*)d_in[0];
    const float* shift_vec  = (const float*)d_in[1];
    const int*   gidx       = (const int*)  d_in[2];
    const float* ce_w1      = (const float*)d_in[3];
    const float* ce_b1      = (const float*)d_in[4];
    const float* ce_w2      = (const float*)d_in[5];
    const float* ce_b2      = (const float*)d_in[6];
    const float* gene_table = (const float*)d_in[7];
    const float* g_w1       = (const float*)d_in[8];
    const float* g_b1       = (const float*)d_in[9];
    const float* g_w2       = (const float*)d_in[10];
    const float* g_b2       = (const float*)d_in[11];
    const float* g_w3       = (const float*)d_in[12];
    float* out = (float*)d_out;

    const int G  = in_sizes[2];
    const int Gc = in_sizes[0] / C_CELLS;

    int nsm = 148;
    cudaDeviceGetAttribute(&nsm, cudaDevAttrMultiProcessorCount, 0);
    if (nsm <= 0) nsm = 148;
    int grid = nsm < G ? nsm : G;

    cudaFuncSetAttribute(k_main, cudaFuncAttributeMaxDynamicSharedMemorySize, SM_TOTAL);
    cudaFuncSetAttribute(k_prep1, cudaFuncAttributeMaxDynamicSharedMemorySize,
                         Gc * (int)sizeof(float));

    k_prep1<<<C_CELLS, H_DIM, Gc * sizeof(float)>>>(ctrl, ce_w1, ce_b1, ce_w2, ce_b2, g_w1, Gc);
    k_prep2<<<G + H_DIM, H_DIM>>>(gene_table, shift_vec, gidx, g_w1, g_b1, g_w2, G);
    k_main<<<grid, 512, SM_TOTAL>>>(ctrl, gidx, g_w1, g_w2, g_b2, g_w3, out, G, Gc);
}

// round 6
// speedup vs baseline: 2.6749x; 1.3460x over previous
#include <cuda_runtime.h>
#include <cuda_fp16.h>
#include <cstdint>
#include <math.h>

#define C_CELLS 128
#define H_DIM   256
#define CE_DIM  64
#define MAXG    2048
#define KB      16          // K-split blocks in prepA

// ---------------- device scratch (allocation-free rule) ----------------
__device__ float  g_part[KB * C_CELLS * H_DIM];          // prepA partials
__device__ __half g_Ah[C_CELLS * H_DIM];                 // A fp16, layout [c/2][h][c&1]
__device__ float  g_Bbuf[MAXG * H_DIM];                  // gene-side layer1 bias [g][h]
__device__ __align__(16) __half g_w2t[H_DIM * H_DIM];    // fp16 W2a^T [n][k] plain

__device__ __forceinline__ float eluf(float x) {
    return x > 0.f ? x : (__expf(x) - 1.f);
}
__device__ __forceinline__ uint32_t smem_to_u32(const void* p) {
    uint32_t a;
    asm("{ .reg .u64 t; cvta.to.shared.u64 t, %1; cvt.u32.u64 %0, t; }" : "=r"(a) : "l"(p));
    return a;
}
__device__ __forceinline__ void ldsm4(uint32_t* r, uint32_t addr) {
    asm volatile("ldmatrix.sync.aligned.m8n8.x4.shared.b16 {%0,%1,%2,%3}, [%4];"
                 : "=r"(r[0]), "=r"(r[1]), "=r"(r[2]), "=r"(r[3]) : "r"(addr));
}
__device__ __forceinline__ void mma16816(float* c, const uint32_t* a, const uint32_t* b) {
    asm volatile("mma.sync.aligned.m16n8k16.row.col.f32.f16.f16.f32 "
                 "{%0,%1,%2,%3}, {%4,%5,%6,%7}, {%8,%9}, {%0,%1,%2,%3};"
                 : "+f"(c[0]), "+f"(c[1]), "+f"(c[2]), "+f"(c[3])
                 : "r"(a[0]), "r"(a[1]), "r"(a[2]), "r"(a[3]), "r"(b[0]), "r"(b[1]));
}
__device__ __forceinline__ void sts16(uint32_t addr, __half v) {
    unsigned short u = __half_as_ushort(v);
    asm volatile("st.shared.u16 [%0], %1;" :: "r"(addr), "h"(u) : "memory");
}

#define SWZ256(b) ((b) ^ (((b) >> 4) & 0x70))
#define SWZ512(b) ((b) ^ (((b) >> 5) & 0x70))

// ---------------- SMEM layout (byte offsets) ----------------
#define SM_W2T   0          // 256 x 512B swizzled fp16      (131072)
#define SM_BUF0  131072     // h1 k-chunk0: 128 x 256B swz   (32768)
#define SM_BUF1  163840     // h1 k-chunk1                   (32768)
#define SM_CTRL  196608     // 128 f32
#define SM_PART  197120     // 512 f32
#define SM_P1    199168     // 256 f32
#define SM_R     200192     // 256 f32
#define SM_W3A   201216     // 256 f32
#define SM_LOGIT 202240     // 128 f32
#define SM_RED   202752     // 32 f32
#define SM_TOTAL 202880

// ---------------------------------------------------------------------------
// prepA: partial GEMM hidden_pre = ctrl @ ce_w1, K-split.
// grid (KB, 16), 256 threads, smem = 8*kc floats. Block (kb, cb): 8 cells.
// ---------------------------------------------------------------------------
__global__ void k_prepA(const float* __restrict__ ctrl, const float* __restrict__ w,
                        int G, int kc) {
    extern __shared__ float sc[];                  // [8][kc]
    const int kb = blockIdx.x, cb = blockIdx.y, t = threadIdx.x;
    const int k0 = kb * kc;
    int kn = G - k0; if (kn > kc) kn = kc; if (kn < 0) kn = 0;

    for (int i = t; i < 8 * kn; i += 256) {
        int ci = i / kn, k = i - ci * kn;
        sc[ci * kc + k] = ctrl[(cb * 8 + ci) * G + k0 + k];
    }
    __syncthreads();

    float acc[8] = {0.f, 0.f, 0.f, 0.f, 0.f, 0.f, 0.f, 0.f};
    int k = 0;
    for (; k + 1 < kn; k += 2) {
        const float w0 = w[(k0 + k) * H_DIM + t];
        const float w1 = w[(k0 + k + 1) * H_DIM + t];
        #pragma unroll
        for (int ci = 0; ci < 8; ci++) {
            const float2 cv = *(const float2*)&sc[ci * kc + k];   // kc even
            acc[ci] = fmaf(cv.x, w0, acc[ci]);
            acc[ci] = fmaf(cv.y, w1, acc[ci]);
        }
    }
    if (k < kn) {
        const float w0 = w[(k0 + k) * H_DIM + t];
        #pragma unroll
        for (int ci = 0; ci < 8; ci++) acc[ci] = fmaf(sc[ci * kc + k], w0, acc[ci]);
    }
    #pragma unroll
    for (int ci = 0; ci < 8; ci++)
        g_part[(kb * C_CELLS + cb * 8 + ci) * H_DIM + t] = acc[ci];
}

// ---------------------------------------------------------------------------
// prepB: per cell: reduce partials + b1, elu -> hid; ce = hid@ce_w2+b2;
//        A[c,h] = ce @ W1[1:65,h] -> fp16 g_Ah (paired layout).
// grid 128 x 256 threads
// ---------------------------------------------------------------------------
__global__ void k_prepB(const float* __restrict__ b1,
                        const float* __restrict__ ce_w2, const float* __restrict__ ce_b2,
                        const float* __restrict__ gw1) {
    __shared__ float s_hid[H_DIM];
    __shared__ float s_ce[CE_DIM];
    const int c = blockIdx.x, t = threadIdx.x;
    float a = b1[t];
    #pragma unroll
    for (int kb = 0; kb < KB; kb++) a += g_part[(kb * C_CELLS + c) * H_DIM + t];
    s_hid[t] = eluf(a);
    __syncthreads();
    if (t < CE_DIM) {
        float v = ce_b2[t];
        #pragma unroll 4
        for (int kk = 0; kk < H_DIM; kk++) v = fmaf(s_hid[kk], ce_w2[kk * CE_DIM + t], v);
        s_ce[t] = v;
    }
    __syncthreads();
    float av = 0.f;
    #pragma unroll
    for (int j = 0; j < CE_DIM; j++) av = fmaf(s_ce[j], gw1[(1 + j) * H_DIM + t], av);
    g_Ah[(c >> 1) * (2 * H_DIM) + t * 2 + (c & 1)] = __float2half(av);
}

// ---------------------------------------------------------------------------
// prep2: blocks [0,G): B rows; blocks [G, G+256): w2t rows.
// ---------------------------------------------------------------------------
__global__ void k_prep2(const float* __restrict__ gene_table, const float* __restrict__ shift_vec,
                        const int* __restrict__ gidx, const float* __restrict__ gw1,
                        const float* __restrict__ gb1, const float* __restrict__ gw2, int G) {
    const int t = threadIdx.x;
    if ((int)blockIdx.x < G) {
        __shared__ float s_ge[CE_DIM];
        __shared__ float s_shift;
        const int g = blockIdx.x;
        const int gi = gidx[g];
        if (t < CE_DIM) s_ge[t] = gene_table[gi * CE_DIM + t];
        if (t == 0) s_shift = shift_vec[gi];
        __syncthreads();
        float a = gb1[t] + s_shift * gw1[129 * H_DIM + t] + (float)C_CELLS * gw1[130 * H_DIM + t];
        #pragma unroll
        for (int j = 0; j < CE_DIM; j++) a = fmaf(s_ge[j], gw1[(65 + j) * H_DIM + t], a);
        g_Bbuf[g * H_DIM + t] = a;
    } else {
        const int n = blockIdx.x - G;
        g_w2t[n * H_DIM + t] = __float2half(gw2[t * H_DIM + n]);
    }
}

// ---------------------------------------------------------------------------
// k_main: persistent; A cached in 32 half2 registers; r overlapped with GEMM.
// ---------------------------------------------------------------------------
__global__ void __launch_bounds__(512, 1)
k_main(const float* __restrict__ ctrl, const int* __restrict__ gidx,
       const float* __restrict__ gw1, const float* __restrict__ gw2,
       const float* __restrict__ gb2, const float* __restrict__ gw3,
       float* __restrict__ out, int G, int Gc) {
    extern __shared__ char smem[];
    const uint32_t smem_u = smem_to_u32(smem);
    const int t = threadIdx.x;
    const int lane = t & 31, w = t >> 5;

    float* s_ctrl  = (float*)(smem + SM_CTRL);
    float* s_part  = (float*)(smem + SM_PART);
    float* s_p1    = (float*)(smem + SM_P1);
    float* s_r     = (float*)(smem + SM_R);
    float* s_w3a   = (float*)(smem + SM_W3A);
    float* s_logit = (float*)(smem + SM_LOGIT);
    float* s_red   = (float*)(smem + SM_RED);

    // ---- one-time init ----
    {
        const uint4* src = (const uint4*)g_w2t;
        for (int idx = t; idx < 8192; idx += 512) {
            int n = idx >> 5, kq = idx & 31;
            uint32_t local = (uint32_t)n * 512u + (uint32_t)kq * 16u;
            *(uint4*)(smem + SM_W2T + SWZ512(local)) = src[idx];
        }
        if (t < 256) s_w3a[t] = gw3[t];
        if (t < 128) s_logit[t] = 0.f;
    }

    // ---- per-thread constants ----
    const int h   = t & 255, sub = t >> 8;        // pass1: h column, cell half
    const float w10 = gw1[h];
    const uint32_t stsbase = smem_u + (h < 128 ? SM_BUF0 : SM_BUF1);
    const uint32_t kb2 = (uint32_t)(h & 127) * 2u;

    // A cache: 32 half2 = cells sub*64 .. sub*64+63 (pairs), column h
    __half2 aReg[32];
    {
        const __half2* Ap = (const __half2*)g_Ah + (uint32_t)(sub * 32) * 256u + h;
        #pragma unroll
        for (int q = 0; q < 32; q++) aReg[q] = Ap[q * 256];
    }

    const int mrow = (w & 3) * 32, nb = (w >> 2) * 64;
    const uint32_t a_rb = (uint32_t)(mrow + (lane & 15)) * 256u + (uint32_t)((lane >> 4) * 16);
    const uint32_t b_rb = (uint32_t)(nb + ((lane >> 4) << 3) + (lane & 7)) * 512u
                        + (uint32_t)(((lane >> 3) & 1) * 16);

    const int  rcol  = w * 16 + (lane >> 1);
    const int  rkh   = lane & 1;
    const float rbias = (rkh == 0) ? gb2[rcol] : 0.f;
    const float* w2bp = gw2 + 256 * H_DIM + rkh * 128 * H_DIM + rcol;
    __syncthreads();

    for (int g = blockIdx.x; g < G; g += gridDim.x) {
        const int gi = gidx[g];
        if (t < 128) s_ctrl[t] = ctrl[t * Gc + gi];
        __syncthreads();

        // ---- pass1: h1 fp16 into BUF0/BUF1 + partial column sums (no LDG) ----
        {
            const float Brow = g_Bbuf[g * H_DIM + h];
            float sum = 0.f;
            #pragma unroll 8
            for (int q = 0; q < 32; q++) {
                const float2 av = __half22float2(aReg[q]);
                const int c0 = sub * 64 + q * 2;
                float v0 = fmaf(s_ctrl[c0],     w10, av.x + Brow);
                float v1 = fmaf(s_ctrl[c0 + 1], w10, av.y + Brow);
                v0 = eluf(v0); v1 = eluf(v1);
                sum += v0 + v1;
                sts16(stsbase + (uint32_t)c0 * 256u + (kb2 ^ ((uint32_t)(c0 & 7) << 4)),
                      __float2half(v0));
                sts16(stsbase + (uint32_t)(c0 + 1) * 256u + (kb2 ^ ((uint32_t)((c0 + 1) & 7) << 4)),
                      __float2half(v1));
            }
            s_part[sub * 256 + h] = sum;
        }
        __syncthreads();
        if (t < 256) s_p1[t] = (s_part[t] + s_part[256 + t]) * (1.f / (float)C_CELLS);
        __syncthreads();

        // ---- GEMM (16 k-steps) with r interleaved into chunk0 ----
        float acc[2][8][4];
        #pragma unroll
        for (int mh = 0; mh < 2; mh++)
            #pragma unroll
            for (int j = 0; j < 8; j++)
                #pragma unroll
                for (int q = 0; q < 4; q++) acc[mh][j][q] = 0.f;

        float racc = rbias;
        #pragma unroll
        for (int ksl = 0; ksl < 8; ksl++) {
            uint32_t a0o = a_rb + (uint32_t)ksl * 32;
            uint32_t a[2][4];
            ldsm4(a[0], smem_u + SM_BUF0 + SWZ256(a0o));
            ldsm4(a[1], smem_u + SM_BUF0 + SWZ256(a0o + 16u * 256u));
            uint32_t bk = b_rb + (uint32_t)ksl * 32;
            #pragma unroll
            for (int j2 = 0; j2 < 4; j2++) {
                uint32_t b[4];
                ldsm4(b, smem_u + SM_W2T + SWZ512(bk + (uint32_t)j2 * (16u * 512u)));
                mma16816(acc[0][j2 * 2],     a[0], b);
                mma16816(acc[0][j2 * 2 + 1], a[0], b + 2);
                mma16816(acc[1][j2 * 2],     a[1], b);
                mma16816(acc[1][j2 * 2 + 1], a[1], b + 2);
            }
            #pragma unroll
            for (int ii = 0; ii < 16; ii++) {
                const int i = ksl * 16 + ii;
                racc = fmaf(s_p1[rkh * 128 + i], w2bp[i * H_DIM], racc);
            }
        }
        #pragma unroll
        for (int ksl = 0; ksl < 8; ksl++) {
            uint32_t a0o = a_rb + (uint32_t)ksl * 32;
            uint32_t a[2][4];
            ldsm4(a[0], smem_u + SM_BUF1 + SWZ256(a0o));
            ldsm4(a[1], smem_u + SM_BUF1 + SWZ256(a0o + 16u * 256u));
            uint32_t bk = b_rb + (uint32_t)(8 + ksl) * 32;
            #pragma unroll
            for (int j2 = 0; j2 < 4; j2++) {
                uint32_t b[4];
                ldsm4(b, smem_u + SM_W2T + SWZ512(bk + (uint32_t)j2 * (16u * 512u)));
                mma16816(acc[0][j2 * 2],     a[0], b);
                mma16816(acc[0][j2 * 2 + 1], a[0], b + 2);
                mma16816(acc[1][j2 * 2],     a[1], b);
                mma16816(acc[1][j2 * 2 + 1], a[1], b + 2);
            }
        }
        racc += __shfl_xor_sync(0xffffffffu, racc, 1);
        if (rkh == 0) s_r[rcol] = racc;
        __syncthreads();

        // ---- epilogue: fold elu(x2 + r[n]) * w3a[n] -> per-cell logits ----
        {
            float p[4] = {0.f, 0.f, 0.f, 0.f};
            const int nc = nb + ((lane & 3) << 1);
            #pragma unroll
            for (int mh = 0; mh < 2; mh++)
                #pragma unroll
                for (int j = 0; j < 8; j++) {
                    const int n0 = nc + j * 8;
                    const float w30 = s_w3a[n0], w31 = s_w3a[n0 + 1];
                    const float rr0 = s_r[n0],  rr1 = s_r[n0 + 1];
                    p[mh*2+0] = fmaf(eluf(acc[mh][j][0] + rr0), w30, p[mh*2+0]);
                    p[mh*2+0] = fmaf(eluf(acc[mh][j][1] + rr1), w31, p[mh*2+0]);
                    p[mh*2+1] = fmaf(eluf(acc[mh][j][2] + rr0), w30, p[mh*2+1]);
                    p[mh*2+1] = fmaf(eluf(acc[mh][j][3] + rr1), w31, p[mh*2+1]);
                }
            #pragma unroll
            for (int i = 0; i < 4; i++) {
                p[i] += __shfl_xor_sync(0xffffffffu, p[i], 1);
                p[i] += __shfl_xor_sync(0xffffffffu, p[i], 2);
            }
            if ((lane & 3) == 0) {
                #pragma unroll
                for (int i = 0; i < 4; i++)
                    atomicAdd(&s_logit[mrow + (i >> 1) * 16 + (i & 1) * 8 + (lane >> 2)], p[i]);
            }
        }
        __syncthreads();

        // ---- softmax over 128 cells ----
        {
            float l = (t < 128) ? s_logit[t] : -1e30f;
            float m = l;
            #pragma unroll
            for (int off = 16; off; off >>= 1) m = fmaxf(m, __shfl_xor_sync(0xffffffffu, m, off));
            if (lane == 0) s_red[w] = m;
            __syncthreads();
            if (t < 32) {
                float mm = (t < 16) ? s_red[t] : -1e30f;
                #pragma unroll
                for (int off = 8; off; off >>= 1) mm = fmaxf(mm, __shfl_xor_sync(0xffffffffu, mm, off));
                if (t == 0) s_red[16] = mm;
            }
            __syncthreads();
            const float M = s_red[16];
            float e = (t < 128) ? __expf(l - M) : 0.f;
            float s = e;
            #pragma unroll
            for (int off = 16; off; off >>= 1) s += __shfl_xor_sync(0xffffffffu, s, off);
            if (lane == 0) s_red[w] = s;
            __syncthreads();
            if (t < 32) {
                float ss = (t < 16) ? s_red[t] : 0.f;
                #pragma unroll
                for (int off = 8; off; off >>= 1) ss += __shfl_xor_sync(0xffffffffu, ss, off);
                if (t == 0) s_red[17] = ss;
            }
            __syncthreads();
            if (t < 128) {
                out[t * G + g] = e / s_red[17];
                s_logit[t] = 0.f;
            }
        }
    }
}

// ---------------------------------------------------------------------------
extern "C" void kernel_launch(void* const* d_in, const int* in_sizes, int n_in,
                              void* d_out, int out_size) {
    const float* ctrl       = (const float*)d_in[0];
    const float* shift_vec  = (const float*)d_in[1];
    const int*   gidx       = (const int*)  d_in[2];
    const float* ce_w1      = (const float*)d_in[3];
    const float* ce_b1      = (const float*)d_in[4];
    const float* ce_w2      = (const float*)d_in[5];
    const float* ce_b2      = (const float*)d_in[6];
    const float* gene_table = (const float*)d_in[7];
    const float* g_w1       = (const float*)d_in[8];
    const float* g_b1       = (const float*)d_in[9];
    const float* g_w2       = (const float*)d_in[10];
    const float* g_b2       = (const float*)d_in[11];
    const float* g_w3       = (const float*)d_in[12];
    float* out = (float*)d_out;

    const int G  = in_sizes[2];
    const int Gc = in_sizes[0] / C_CELLS;
    int kc = (Gc + KB - 1) / KB;
    kc = (kc + 1) & ~1;                      // even for float2 smem reads

    int nsm = 148;
    cudaDeviceGetAttribute(&nsm, cudaDevAttrMultiProcessorCount, 0);
    if (nsm <= 0) nsm = 148;
    int grid = nsm < G ? nsm : G;

    cudaFuncSetAttribute(k_main, cudaFuncAttributeMaxDynamicSharedMemorySize, SM_TOTAL);
    cudaFuncSetAttribute(k_prepA, cudaFuncAttributeMaxDynamicSharedMemorySize,
                         8 * kc * (int)sizeof(float));

    k_prepA<<<dim3(KB, 16), 256, 8 * kc * sizeof(float)>>>(ctrl, ce_w1, Gc, kc);
    k_prepB<<<C_CELLS, H_DIM>>>(ce_b1, ce_w2, ce_b2, g_w1);
    k_prep2<<<G + H_DIM, H_DIM>>>(gene_table, shift_vec, gidx, g_w1, g_b1, g_w2, G);
    k_main<<<grid, 512, SM_TOTAL>>>(ctrl, gidx, g_w1, g_w2, g_b2, g_w3, out, G, Gc);
}

// round 7
// speedup vs baseline: 2.8251x; 1.0562x over previous
#include <cuda_runtime.h>
#include <cuda_fp16.h>
#include <cstdint>
#include <math.h>

#define C_CELLS 128
#define H_DIM   256
#define CE_DIM  64
#define MAXG    2048
#define KB      16

// ---------------- device scratch ----------------
__device__ float  g_part[KB * C_CELLS * H_DIM];
__device__ __half g_Ah[C_CELLS * H_DIM];               // A fp16, [c/2][h][c&1]
__device__ float  g_Bbuf[MAXG * H_DIM];
__device__ __align__(16) __half g_w2t[H_DIM * H_DIM];  // fp16 W2a^T [n][k]

__device__ __forceinline__ float eluf(float x) {
    return x > 0.f ? x : (__expf(x) - 1.f);
}
__device__ __forceinline__ uint32_t smem_to_u32(const void* p) {
    uint32_t a;
    asm("{ .reg .u64 t; cvta.to.shared.u64 t, %1; cvt.u32.u64 %0, t; }" : "=r"(a) : "l"(p));
    return a;
}
__device__ __forceinline__ void ldsm4(uint32_t* r, uint32_t addr) {
    asm volatile("ldmatrix.sync.aligned.m8n8.x4.shared.b16 {%0,%1,%2,%3}, [%4];"
                 : "=r"(r[0]), "=r"(r[1]), "=r"(r[2]), "=r"(r[3]) : "r"(addr));
}
__device__ __forceinline__ void ldsm4t(uint32_t* r, uint32_t addr) {
    asm volatile("ldmatrix.sync.aligned.m8n8.x4.trans.shared.b16 {%0,%1,%2,%3}, [%4];"
                 : "=r"(r[0]), "=r"(r[1]), "=r"(r[2]), "=r"(r[3]) : "r"(addr));
}
__device__ __forceinline__ void mma16816(float* c, const uint32_t* a, const uint32_t* b) {
    asm volatile("mma.sync.aligned.m16n8k16.row.col.f32.f16.f16.f32 "
                 "{%0,%1,%2,%3}, {%4,%5,%6,%7}, {%8,%9}, {%0,%1,%2,%3};"
                 : "+f"(c[0]), "+f"(c[1]), "+f"(c[2]), "+f"(c[3])
                 : "r"(a[0]), "r"(a[1]), "r"(a[2]), "r"(a[3]), "r"(b[0]), "r"(b[1]));
}
__device__ __forceinline__ void sts32h2(uint32_t addr, __half2 v) {
    uint32_t u = *reinterpret_cast<uint32_t*>(&v);
    asm volatile("st.shared.u32 [%0], %1;" :: "r"(addr), "r"(u) : "memory");
}
__device__ __forceinline__ __half2 h2ex2(__half2 x) {
    uint32_t xi = *reinterpret_cast<uint32_t*>(&x), ri;
    asm("ex2.approx.f16x2 %0, %1;" : "=r"(ri) : "r"(xi));
    return *reinterpret_cast<__half2*>(&ri);
}

#define SWZ512(b) ((b) ^ (((b) >> 5) & 0x70))

// ---------------- SMEM layout ----------------
#define SM_W2T   0          // 131072
#define SM_BUF   131072     // h1 transposed [256 h][128 c]*2B = 65536
#define SM_CTRLH 196608     // 128 halves (256 B)
#define SM_PART  196864     // 512 f32
#define SM_P1    198912     // 256 f32
#define SM_R     199936     // 256 f32
#define SM_W3A   200960     // 256 f32
#define SM_LOGIT 201984     // 128 f32
#define SM_RED   202496     // 32 f32
#define SM_TOTAL 202624

// ---------------------------------------------------------------------------
__global__ void k_prepA(const float* __restrict__ ctrl, const float* __restrict__ w,
                        int G, int kc) {
    extern __shared__ float sc[];
    const int kb = blockIdx.x, cb = blockIdx.y, t = threadIdx.x;
    const int k0 = kb * kc;
    int kn = G - k0; if (kn > kc) kn = kc; if (kn < 0) kn = 0;
    for (int i = t; i < 8 * kn; i += 256) {
        int ci = i / kn, k = i - ci * kn;
        sc[ci * kc + k] = ctrl[(cb * 8 + ci) * G + k0 + k];
    }
    __syncthreads();
    float acc[8] = {0.f,0.f,0.f,0.f,0.f,0.f,0.f,0.f};
    int k = 0;
    for (; k + 1 < kn; k += 2) {
        const float w0 = w[(k0 + k) * H_DIM + t];
        const float w1 = w[(k0 + k + 1) * H_DIM + t];
        #pragma unroll
        for (int ci = 0; ci < 8; ci++) {
            const float2 cv = *(const float2*)&sc[ci * kc + k];
            acc[ci] = fmaf(cv.x, w0, acc[ci]);
            acc[ci] = fmaf(cv.y, w1, acc[ci]);
        }
    }
    if (k < kn) {
        const float w0 = w[(k0 + k) * H_DIM + t];
        #pragma unroll
        for (int ci = 0; ci < 8; ci++) acc[ci] = fmaf(sc[ci * kc + k], w0, acc[ci]);
    }
    #pragma unroll
    for (int ci = 0; ci < 8; ci++)
        g_part[(kb * C_CELLS + cb * 8 + ci) * H_DIM + t] = acc[ci];
}

__global__ void k_prepB(const float* __restrict__ b1,
                        const float* __restrict__ ce_w2, const float* __restrict__ ce_b2,
                        const float* __restrict__ gw1) {
    __shared__ float s_hid[H_DIM];
    __shared__ float s_ce[CE_DIM];
    const int c = blockIdx.x, t = threadIdx.x;
    float a = b1[t];
    #pragma unroll
    for (int kb = 0; kb < KB; kb++) a += g_part[(kb * C_CELLS + c) * H_DIM + t];
    s_hid[t] = eluf(a);
    __syncthreads();
    if (t < CE_DIM) {
        float v = ce_b2[t];
        #pragma unroll 4
        for (int kk = 0; kk < H_DIM; kk++) v = fmaf(s_hid[kk], ce_w2[kk * CE_DIM + t], v);
        s_ce[t] = v;
    }
    __syncthreads();
    float av = 0.f;
    #pragma unroll
    for (int j = 0; j < CE_DIM; j++) av = fmaf(s_ce[j], gw1[(1 + j) * H_DIM + t], av);
    g_Ah[(c >> 1) * (2 * H_DIM) + t * 2 + (c & 1)] = __float2half(av);
}

__global__ void k_prep2(const float* __restrict__ gene_table, const float* __restrict__ shift_vec,
                        const int* __restrict__ gidx, const float* __restrict__ gw1,
                        const float* __restrict__ gb1, const float* __restrict__ gw2, int G) {
    const int t = threadIdx.x;
    if ((int)blockIdx.x < G) {
        __shared__ float s_ge[CE_DIM];
        __shared__ float s_shift;
        const int g = blockIdx.x;
        const int gi = gidx[g];
        if (t < CE_DIM) s_ge[t] = gene_table[gi * CE_DIM + t];
        if (t == 0) s_shift = shift_vec[gi];
        __syncthreads();
        float a = gb1[t] + s_shift * gw1[129 * H_DIM + t] + (float)C_CELLS * gw1[130 * H_DIM + t];
        #pragma unroll
        for (int j = 0; j < CE_DIM; j++) a = fmaf(s_ge[j], gw1[(65 + j) * H_DIM + t], a);
        g_Bbuf[g * H_DIM + t] = a;
    } else {
        const int n = blockIdx.x - G;
        g_w2t[n * H_DIM + t] = __float2half(gw2[t * H_DIM + n]);
    }
}

// ---------------------------------------------------------------------------
__global__ void __launch_bounds__(512, 1)
k_main(const float* __restrict__ ctrl, const int* __restrict__ gidx,
       const float* __restrict__ gw1, const float* __restrict__ gw2,
       const float* __restrict__ gb2, const float* __restrict__ gw3,
       float* __restrict__ out, int G, int Gc) {
    extern __shared__ char smem[];
    const uint32_t smem_u = smem_to_u32(smem);
    const int t = threadIdx.x;
    const int lane = t & 31, w = t >> 5;

    __half2* s_ctrlh2 = (__half2*)(smem + SM_CTRLH);
    __half*  s_ctrlh  = (__half*)(smem + SM_CTRLH);
    float* s_part  = (float*)(smem + SM_PART);
    float* s_p1    = (float*)(smem + SM_P1);
    float* s_r     = (float*)(smem + SM_R);
    float* s_w3a   = (float*)(smem + SM_W3A);
    float* s_logit = (float*)(smem + SM_LOGIT);
    float* s_red   = (float*)(smem + SM_RED);

    // ---- one-time init ----
    {
        const uint4* src = (const uint4*)g_w2t;
        for (int idx = t; idx < 8192; idx += 512) {
            int n = idx >> 5, kq = idx & 31;
            uint32_t local = (uint32_t)n * 512u + (uint32_t)kq * 16u;
            *(uint4*)(smem + SM_W2T + SWZ512(local)) = src[idx];
        }
        if (t < 256) s_w3a[t] = gw3[t];
        if (t < 128) s_logit[t] = 0.f;
    }

    // ---- pass1 constants ----
    const int h = t & 255, mhalf = t >> 8;
    const int rot = (h >> 3) & 3;
    const __half2 w102 = __float2half2_rn(gw1[h]);
    const __half2 L2E2 = __float2half2_rn(1.44269504f);
    const __half2 HNEG1 = __float2half2_rn(-1.f);
    const __half2 HZERO = __float2half2_rn(0.f);
    const uint32_t xm = (uint32_t)(h & 7) << 4;
    const uint32_t rowbase = smem_u + SM_BUF + (uint32_t)h * 256u;

    // A cache: aReg[q] = cell pair (mhalf*64 + ((q+rot)&31)*2), column h
    __half2 aReg[32];
    {
        const __half2* Ap = (const __half2*)g_Ah;
        #pragma unroll
        for (int q = 0; q < 32; q++) {
            int cp = mhalf * 32 + ((q + rot) & 31);
            aReg[q] = Ap[(uint32_t)cp * 256u + h];
        }
    }

    // GEMM constants
    const int mrow = (w & 3) * 32, nb = (w >> 2) * 64;
    const int krl = (lane & 7) + ((lane >> 4) << 3);           // 0..15
    const uint32_t xmA = (uint32_t)(krl & 7) << 4;
    const uint32_t mcoff = (uint32_t)(mrow + (((lane >> 3) & 1) << 3)) * 2u;
    const uint32_t aBase0 = smem_u + SM_BUF + (uint32_t)krl * 256u + (mcoff ^ xmA);
    const uint32_t aBase1 = smem_u + SM_BUF + (uint32_t)krl * 256u + ((mcoff + 32u) ^ xmA);
    const uint32_t b_rb = (uint32_t)(nb + ((lane >> 4) << 3) + (lane & 7)) * 512u
                        + (uint32_t)(((lane >> 3) & 1) * 16);

    const int  rcol  = w * 16 + (lane >> 1);
    const int  rkh   = lane & 1;
    const float rbias = (rkh == 0) ? gb2[rcol] : 0.f;
    const float* w2bp = gw2 + 256 * H_DIM + rkh * 128 * H_DIM + rcol;

    // ---- gene-0 state + prefetch ----
    float bcur = 0.f, cpref = 0.f;
    {
        const int g0 = blockIdx.x;
        const int gi0 = gidx[g0];
        bcur = g_Bbuf[g0 * H_DIM + h];
        if (t < 128) cpref = ctrl[t * Gc + gi0];
    }
    __syncthreads();

    for (int g = blockIdx.x; g < G; g += gridDim.x) {
        if (t < 128) s_ctrlh[t] = __float2half(cpref);
        __syncthreads();                                        // S1

        const int gn = g + gridDim.x;
        const bool hasnext = gn < G;
        int gi_next = 0;
        if (hasnext) gi_next = gidx[gn];                        // hide under pass1

        // ---- pass1: h1 fp16x2 -> BUF (transposed) + fp16 partial sums ----
        {
            const __half2 brow2 = __float2half2_rn(bcur);
            __half2 av[4] = {HZERO, HZERO, HZERO, HZERO};
            #pragma unroll
            for (int q = 0; q < 32; q++) {
                const int qi = (q + rot) & 31;
                __half2 c2 = s_ctrlh2[mhalf * 32 + qi];
                __half2 z2 = __hfma2(c2, w102, __hadd2(aReg[q], brow2));
                __half2 e2 = h2ex2(__hmul2(z2, L2E2));
                __half2 v2 = __hadd2(__hmax2(z2, HZERO),
                                     __hmin2(__hadd2(e2, HNEG1), HZERO));
                av[q & 3] = __hadd2(av[q & 3], v2);
                sts32h2(rowbase + (((uint32_t)(mhalf * 128 + qi * 4)) ^ xm), v2);
            }
            float2 f0 = __half22float2(av[0]), f1 = __half22float2(av[1]);
            float2 f2 = __half22float2(av[2]), f3 = __half22float2(av[3]);
            s_part[mhalf * 256 + h] = ((f0.x + f0.y) + (f1.x + f1.y))
                                    + ((f2.x + f2.y) + (f3.x + f3.y));
        }
        __syncthreads();                                        // S2
        if (t < 256) s_p1[t] = (s_part[t] + s_part[256 + t]) * (1.f / (float)C_CELLS);
        __syncthreads();                                        // S3

        // prefetch next gene data (latency hidden under GEMM)
        float bnext = 0.f;
        if (hasnext) {
            bnext = g_Bbuf[gn * H_DIM + h];
            if (t < 128) cpref = ctrl[t * Gc + gi_next];
        }

        // ---- GEMM (16 k-steps, trans A) with r interleaved ----
        float acc[2][8][4];
        #pragma unroll
        for (int mh = 0; mh < 2; mh++)
            #pragma unroll
            for (int j = 0; j < 8; j++)
                #pragma unroll
                for (int q = 0; q < 4; q++) acc[mh][j][q] = 0.f;

        float racc = rbias;
        #pragma unroll
        for (int ks = 0; ks < 16; ks++) {
            const uint32_t ao = (uint32_t)ks * 4096u;
            uint32_t a0r[4], a1r[4];
            ldsm4t(a0r, aBase0 + ao);
            ldsm4t(a1r, aBase1 + ao);
            const uint32_t bk = b_rb + (uint32_t)ks * 32u;
            #pragma unroll
            for (int j2 = 0; j2 < 4; j2++) {
                uint32_t b[4];
                ldsm4(b, smem_u + SM_W2T + SWZ512(bk + (uint32_t)j2 * (16u * 512u)));
                mma16816(acc[0][j2 * 2],     a0r, b);
                mma16816(acc[0][j2 * 2 + 1], a0r, b + 2);
                mma16816(acc[1][j2 * 2],     a1r, b);
                mma16816(acc[1][j2 * 2 + 1], a1r, b + 2);
            }
            #pragma unroll
            for (int ii = 0; ii < 8; ii++) {
                const int i = ks * 8 + ii;
                racc = fmaf(s_p1[rkh * 128 + i], w2bp[i * H_DIM], racc);
            }
        }
        racc += __shfl_xor_sync(0xffffffffu, racc, 1);
        if (rkh == 0) s_r[rcol] = racc;
        __syncthreads();                                        // S4

        // ---- epilogue ----
        {
            float p[4] = {0.f, 0.f, 0.f, 0.f};
            const int nc = nb + ((lane & 3) << 1);
            #pragma unroll
            for (int mh = 0; mh < 2; mh++)
                #pragma unroll
                for (int j = 0; j < 8; j++) {
                    const int n0 = nc + j * 8;
                    const float w30 = s_w3a[n0], w31 = s_w3a[n0 + 1];
                    const float rr0 = s_r[n0],  rr1 = s_r[n0 + 1];
                    p[mh*2+0] = fmaf(eluf(acc[mh][j][0] + rr0), w30, p[mh*2+0]);
                    p[mh*2+0] = fmaf(eluf(acc[mh][j][1] + rr1), w31, p[mh*2+0]);
                    p[mh*2+1] = fmaf(eluf(acc[mh][j][2] + rr0), w30, p[mh*2+1]);
                    p[mh*2+1] = fmaf(eluf(acc[mh][j][3] + rr1), w31, p[mh*2+1]);
                }
            #pragma unroll
            for (int i = 0; i < 4; i++) {
                p[i] += __shfl_xor_sync(0xffffffffu, p[i], 1);
                p[i] += __shfl_xor_sync(0xffffffffu, p[i], 2);
            }
            if ((lane & 3) == 0) {
                #pragma unroll
                for (int i = 0; i < 4; i++)
                    atomicAdd(&s_logit[mrow + (i >> 1) * 16 + (i & 1) * 8 + (lane >> 2)], p[i]);
            }
        }
        __syncthreads();                                        // S5

        // ---- softmax (no max-subtraction: |logit| << 80) ----
        {
            float e = 0.f;
            if (t < 128) e = __expf(s_logit[t]);
            float s = e;
            #pragma unroll
            for (int off = 16; off; off >>= 1) s += __shfl_xor_sync(0xffffffffu, s, off);
            if (t < 128 && lane == 0) s_red[w] = s;
            __syncthreads();                                    // S6
            if (t < 128) {
                const float tot = (s_red[0] + s_red[1]) + (s_red[2] + s_red[3]);
                out[t * G + g] = e / tot;
                s_logit[t] = 0.f;
            }
        }
        bcur = bnext;
    }
}

// ---------------------------------------------------------------------------
extern "C" void kernel_launch(void* const* d_in, const int* in_sizes, int n_in,
                              void* d_out, int out_size) {
    const float* ctrl       = (const float*)d_in[0];
    const float* shift_vec  = (const float*)d_in[1];
    const int*   gidx       = (const int*)  d_in[2];
    const float* ce_w1      = (const float*)d_in[3];
    const float* ce_b1      = (const float*)d_in[4];
    const float* ce_w2      = (const float*)d_in[5];
    const float* ce_b2      = (const float*)d_in[6];
    const float* gene_table = (const float*)d_in[7];
    const float* g_w1       = (const float*)d_in[8];
    const float* g_b1       = (const float*)d_in[9];
    const float* g_w2       = (const float*)d_in[10];
    const float* g_b2       = (const float*)d_in[11];
    const float* g_w3       = (const float*)d_in[12];
    float* out = (float*)d_out;

    const int G  = in_sizes[2];
    const int Gc = in_sizes[0] / C_CELLS;
    int kc = (Gc + KB - 1) / KB;
    kc = (kc + 1) & ~1;

    int nsm = 148;
    cudaDeviceGetAttribute(&nsm, cudaDevAttrMultiProcessorCount, 0);
    if (nsm <= 0) nsm = 148;
    int grid = nsm < G ? nsm : G;

    cudaFuncSetAttribute(k_main, cudaFuncAttributeMaxDynamicSharedMemorySize, SM_TOTAL);
    cudaFuncSetAttribute(k_prepA, cudaFuncAttributeMaxDynamicSharedMemorySize,
                         8 * kc * (int)sizeof(float));

    k_prepA<<<dim3(KB, 16), 256, 8 * kc * sizeof(float)>>>(ctrl, ce_w1, Gc, kc);
    k_prepB<<<C_CELLS, H_DIM>>>(ce_b1, ce_w2, ce_b2, g_w1);
    k_prep2<<<G + H_DIM, H_DIM>>>(gene_table, shift_vec, gidx, g_w1, g_b1, g_w2, G);
    k_main<<<grid, 512, SM_TOTAL>>>(ctrl, gidx, g_w1, g_w2, g_b2, g_w3, out, G, Gc);
}